// round 11
// baseline (speedup 1.0000x reference)
#include <cuda_runtime.h>

#define NCLS 256

// ---------------------------------------------------------------------------
// Closed-form Cholesky of C0 = (K+0.001)*I - 11^T  (g = fp32(K+0.001)):
//   L0[j,j] = d_j, L0[i,j] = c_j (i>j), column-constant below the diagonal.
//   c_j = -sqrt(g/((g-j)(g-1-j))) = -rsqrt((g-j)(g-1-j)/g)
//   d_j = sqrt(g(g-1-j)/(g-j))    =  -(g-1-j) * c_j        [d stored nowhere]
// Matvec y = L0 @ n collapses to a weighted prefix sum:
//   y_j = sum_{k<j} c_k n_k + d_j n_j
// This kernel: 4 rows per warp (single-wave grid, 4-way chain interleave),
// lane owns 8 contiguous classes, tables derived on the fly via MUFU.RSQ.
// ---------------------------------------------------------------------------
__global__ __launch_bounds__(256, 4) void dbf_kernel(
    const int* __restrict__ data, const float* __restrict__ t,
    const float* __restrict__ noise, float* __restrict__ out, int rows)
{
    const float G   = 256.001f;          // fp32(K + 0.001)
    const float GM1 = G - 1.0f;

    int warp = (int)((blockIdx.x * blockDim.x + threadIdx.x) >> 5);
    int lane = threadIdx.x & 31;
    int r0 = warp * 4;
    if (r0 >= rows) return;

    // Per-row scalars: one vector broadcast load each (r0 is 4-aligned)
    float tvv[4]; int xx[4];
    if (r0 + 3 < rows) {
        float4 t4 = *(const float4*)(t + r0);
        int4   x4 = *(const int4*)(data + r0);
        tvv[0] = t4.x; tvv[1] = t4.y; tvv[2] = t4.z; tvv[3] = t4.w;
        xx[0] = x4.x; xx[1] = x4.y; xx[2] = x4.z; xx[3] = x4.w;
    } else {
#pragma unroll
        for (int r = 0; r < 4; r++) {
            int rr = (r0 + r < rows) ? (r0 + r) : (rows - 1);
            tvv[r] = __ldg(t + rr); xx[r] = __ldg(data + rr);
        }
    }

    float sb[4], beta[4]; bool lo[4];
#pragma unroll
    for (int r = 0; r < 4; r++) {
        float s = fminf(tvv[r], 1.0f - 1e-6f);
        lo[r] = s < 1e-10f;
        s = fmaxf(s, 1e-10f);
        sb[r] = s;
        beta[r] = s * s;
    }

    // Front-batch all noise loads (8x LDG.128, MLP ~16 with the scalars)
    int jbase = lane * 8;
    const float4* np = (const float4*)noise + (size_t)r0 * (NCLS / 4) + lane * 2;
    float4 va[4], vb[4];
#pragma unroll
    for (int r = 0; r < 4; r++) {
        int rr4 = (r0 + r < rows) ? r : 0;   // clamp (rows%4==0 in practice)
        va[r] = np[(size_t)rr4 * (NCLS / 4)];
        vb[r] = np[(size_t)rr4 * (NCLS / 4) + 1];
    }
    float n[4][8];
#pragma unroll
    for (int r = 0; r < 4; r++) {
        n[r][0] = va[r].x; n[r][1] = va[r].y; n[r][2] = va[r].z; n[r][3] = va[r].w;
        n[r][4] = vb[r].x; n[r][5] = vb[r].y; n[r][6] = vb[r].z; n[r][7] = vb[r].w;
    }

    // c_j on the fly: one MUFU.RSQ per class, once per warp (reused by 4 rows)
    float c[8];
    const float invg = 1.0f / G;
#pragma unroll
    for (int i = 0; i < 8; i++) {
        float jf = (float)(jbase + i);
        float af = G - jf;               // g - j
        float bf = GM1 - jf;             // g - 1 - j
        c[i] = -rsqrtf(af * bf * invg);
    }

    // Thread-local totals of c_j*n_j (prefix recomputed later)
    float acc[4] = {0.0f, 0.0f, 0.0f, 0.0f};
#pragma unroll
    for (int i = 0; i < 8; i++) {
#pragma unroll
        for (int r = 0; r < 4; r++) acc[r] = fmaf(c[i], n[r][i], acc[r]);
    }

    // Warp exclusive scan, 4 chains interleaved per level
    float sc[4] = {acc[0], acc[1], acc[2], acc[3]};
#pragma unroll
    for (int o = 1; o < 32; o <<= 1) {
        float v0 = __shfl_up_sync(0xffffffffu, sc[0], o);
        float v1 = __shfl_up_sync(0xffffffffu, sc[1], o);
        float v2 = __shfl_up_sync(0xffffffffu, sc[2], o);
        float v3 = __shfl_up_sync(0xffffffffu, sc[3], o);
        if (lane >= o) { sc[0] += v0; sc[1] += v1; sc[2] += v2; sc[3] += v3; }
    }

    // logits_j = beta*(256*[j==x]-1) + sqrt(beta)*(prefix_j + d_j*n_j)
    //   with d_j*n_j = -b_j * (c_j*n_j);  local prefix recomputed in-flight.
    float a[4]; float mx[4];
#pragma unroll
    for (int r = 0; r < 4; r++) { a[r] = sc[r] - acc[r]; mx[r] = -1e30f; }
    const float jb1 = GM1 - (float)jbase;
#pragma unroll
    for (int i = 0; i < 8; i++) {
        float bf = jb1 - (float)i;       // g - 1 - j, folded constant per i
        float ci = c[i];
#pragma unroll
        for (int r = 0; r < 4; r++) {
            float q = ci * n[r][i];
            float y = fmaf(-bf, q, a[r]); // a + d_j*n_j
            a[r] += q;
            float m = (jbase + i == xx[r]) ? 256.0f * beta[r] : 0.0f;
            float l = fmaf(sb[r], y, m - beta[r]);
            n[r][i] = l;
            mx[r] = fmaxf(mx[r], l);
        }
    }

    // Warp max trees (ALU-only, 4 chains interleaved)
#pragma unroll
    for (int o = 16; o > 0; o >>= 1) {
        float v0 = __shfl_xor_sync(0xffffffffu, mx[0], o);
        float v1 = __shfl_xor_sync(0xffffffffu, mx[1], o);
        float v2 = __shfl_xor_sync(0xffffffffu, mx[2], o);
        float v3 = __shfl_xor_sync(0xffffffffu, mx[3], o);
        mx[0] = fmaxf(mx[0], v0); mx[1] = fmaxf(mx[1], v1);
        mx[2] = fmaxf(mx[2], v2); mx[3] = fmaxf(mx[3], v3);
    }

    // Local exps + sums (all 32 MUFUs independent, outside shuffle chains)
    float s[4] = {0.0f, 0.0f, 0.0f, 0.0f};
#pragma unroll
    for (int i = 0; i < 8; i++) {
#pragma unroll
        for (int r = 0; r < 4; r++) {
            n[r][i] = __expf(n[r][i] - mx[r]);
            s[r] += n[r][i];
        }
    }

    // Warp sum trees
#pragma unroll
    for (int o = 16; o > 0; o >>= 1) {
        float v0 = __shfl_xor_sync(0xffffffffu, s[0], o);
        float v1 = __shfl_xor_sync(0xffffffffu, s[1], o);
        float v2 = __shfl_xor_sync(0xffffffffu, s[2], o);
        float v3 = __shfl_xor_sync(0xffffffffu, s[3], o);
        s[0] += v0; s[1] += v1; s[2] += v2; s[3] += v3;
    }

    // p = e/S, or uniform 1/K where lo_beta
    float scale[4], add[4];
#pragma unroll
    for (int r = 0; r < 4; r++) {
        scale[r] = lo[r] ? 0.0f : __fdividef(1.0f, s[r]);
        add[r]   = lo[r] ? (1.0f / 256.0f) : 0.0f;
    }
#pragma unroll
    for (int i = 0; i < 8; i++) {
#pragma unroll
        for (int r = 0; r < 4; r++) n[r][i] = fmaf(n[r][i], scale[r], add[r]);
    }

    float4* op = (float4*)out + (size_t)r0 * (NCLS / 4) + lane * 2;
#pragma unroll
    for (int r = 0; r < 4; r++) {
        if (r0 + r < rows) {
            op[(size_t)r * (NCLS / 4)]     = make_float4(n[r][0], n[r][1], n[r][2], n[r][3]);
            op[(size_t)r * (NCLS / 4) + 1] = make_float4(n[r][4], n[r][5], n[r][6], n[r][7]);
        }
    }
}

extern "C" void kernel_launch(void* const* d_in, const int* in_sizes, int n_in,
                              void* d_out, int out_size) {
    const int*   data  = (const int*)d_in[0];
    const float* t     = (const float*)d_in[1];
    const float* noise = (const float*)d_in[2];
    float*       out   = (float*)d_out;
    int rows = in_sizes[1];                 // B*S = 16384

    int warps  = (rows + 3) / 4;            // 4 rows per warp
    int blocks = (warps + 7) / 8;           // 8 warps per block -> 512 blocks
    dbf_kernel<<<blocks, 256>>>(data, t, noise, out, rows);
}